// round 12
// baseline (speedup 1.0000x reference)
#include <cuda_runtime.h>
#include <cuda_bf16.h>
#include <cuda_fp16.h>
#include <cstdint>
#include <cstddef>

// Problem constants
#define RB 64      // batch
#define RT 512     // time steps
#define RI 512     // input dim
#define RH 1024    // hidden dim
#define RO 512     // output dim
#define NBUF 4     // h ring-buffer depth

// ---------------------------------------------------------------------------
// Scratch (device globals; no allocation allowed)
// ---------------------------------------------------------------------------
__device__ __half g_xp[(size_t)RB * RT * RH];  // x_proj (fp16), then hidden states (in place)
__device__ unsigned g_h2[NBUF * 512 * 64];     // h fp16 k-pairs: [buf][k2][b]
__device__ unsigned g_wflag[256 * 32];         // per-CTA counting write flags (8 warp releases/step)
__device__ unsigned g_rflag[256 * 32];         // per-CTA read flags, 128B apart

// ---------------------------------------------------------------------------
// Helpers
// ---------------------------------------------------------------------------
// fp16 MMA, fp32 accumulate
__device__ __forceinline__ void mma_f16(float* d,
                                        const unsigned* a, unsigned b0, unsigned b1) {
    asm("mma.sync.aligned.m16n8k16.row.col.f32.f16.f16.f32 "
        "{%0,%1,%2,%3},{%4,%5,%6,%7},{%8,%9},{%0,%1,%2,%3};"
        : "+f"(d[0]), "+f"(d[1]), "+f"(d[2]), "+f"(d[3])
        : "r"(a[0]), "r"(a[1]), "r"(a[2]), "r"(a[3]),
          "r"(b0), "r"(b1));
}
__device__ __forceinline__ void flag_release(unsigned* p, unsigned v) {
    asm volatile("st.release.gpu.global.u32 [%0],%1;" :: "l"(p), "r"(v) : "memory");
}
__device__ __forceinline__ unsigned flag_acquire(const unsigned* p) {
    unsigned v;
    asm volatile("ld.acquire.gpu.global.u32 %0,[%1];" : "=r"(v) : "l"(p) : "memory");
    return v;
}
__device__ __forceinline__ void flag_red_add(unsigned* p) {
    asm volatile("red.release.gpu.global.add.u32 [%0],1;" :: "l"(p) : "memory");
}
__device__ __forceinline__ unsigned ldcg_u32(const unsigned* p) {
    unsigned v;
    asm volatile("ld.global.cg.u32 %0,[%1];" : "=r"(v) : "l"(p));
    return v;
}
__device__ __forceinline__ unsigned h2pack(float a, float b) {
    __half2 h = __floats2half2_rn(a, b);   // low = a, high = b
    return *reinterpret_cast<unsigned*>(&h);
}
__device__ __forceinline__ void st_u16_cs(__half* p, unsigned short v) {
    asm volatile("st.global.cs.u16 [%0],%1;" :: "l"(p), "h"(v) : "memory");
}
__device__ __forceinline__ unsigned short ld_u16_cs(const __half* p) {
    unsigned short v;
    asm volatile("ld.global.cs.u16 %0,[%1];" : "=h"(v) : "l"(p));
    return v;
}

// ---------------------------------------------------------------------------
// Init: zero flags, seed g_h2 buf0 from initial_hidden [b][j]
// ---------------------------------------------------------------------------
__global__ void rnn_init(const float* __restrict__ h0) {
    int bid = blockIdx.x;
    if (bid < 128) {
        int idx = bid * 256 + threadIdx.x;      // 0..32767 pairs
        int k2 = idx >> 6;                       // 0..511
        int b  = idx & 63;
        float v0 = h0[b * RH + 2 * k2];
        float v1 = h0[b * RH + 2 * k2 + 1];
        g_h2[k2 * 64 + b] = h2pack(v0, v1);
    } else {
        for (int i = threadIdx.x; i < 256 * 32; i += 256) {
            g_wflag[i] = 0;
            g_rflag[i] = 0;
        }
    }
}

// ---------------------------------------------------------------------------
// FP16 tensor-core GEMM, fp32 A input, fp16 OUTPUT (unchanged from R11)
// ---------------------------------------------------------------------------
#define ASTR2 12
#define BSTR2 136
__global__ void __launch_bounds__(256) gemm_f16_bias_h16out(
    int M, int N, int K,
    const float* __restrict__ A, const float* __restrict__ B,
    const float* __restrict__ bias, __half* __restrict__ C)
{
    __shared__ unsigned As[128 * ASTR2];
    __shared__ unsigned Bs[8 * BSTR2];

    const int tid  = threadIdx.x;
    const int lane = tid & 31, wid = tid >> 5;
    const int g  = lane >> 2, tg = lane & 3;
    const int wm = (wid & 3) << 5;
    const int wn = (wid >> 2) << 6;
    const int bx = blockIdx.x << 7, by = blockIdx.y << 7;

    const int ar = tid >> 1, ah = (tid & 1) << 3;
    const float* Ag = A + (size_t)(by + ar) * K + ah;
    const int bk2 = tid >> 5, bn = (tid & 31) << 2;
    const float* Bg = B + (size_t)(2 * bk2) * N + bx + bn;

    float4 pa0 = *(const float4*)(Ag);
    float4 pa1 = *(const float4*)(Ag + 4);
    float4 pb0 = *(const float4*)(Bg);
    float4 pb1 = *(const float4*)(Bg + (size_t)N);

    float acc[2][8][4];
#pragma unroll
    for (int i = 0; i < 2; i++)
#pragma unroll
        for (int j = 0; j < 8; j++)
#pragma unroll
            for (int l = 0; l < 4; l++) acc[i][j][l] = 0.f;

    for (int k0 = 0; ; ) {
        {
            uint4 va = make_uint4(h2pack(pa0.x, pa0.y), h2pack(pa0.z, pa0.w),
                                  h2pack(pa1.x, pa1.y), h2pack(pa1.z, pa1.w));
            *(uint4*)&As[ar * ASTR2 + (ah >> 1)] = va;
            uint4 vb = make_uint4(h2pack(pb0.x, pb1.x), h2pack(pb0.y, pb1.y),
                                  h2pack(pb0.z, pb1.z), h2pack(pb0.w, pb1.w));
            *(uint4*)&Bs[bk2 * BSTR2 + bn] = vb;
        }
        __syncthreads();

        bool more = (k0 + 16) < K;
        if (more) {
            pa0 = *(const float4*)(Ag + k0 + 16);
            pa1 = *(const float4*)(Ag + k0 + 20);
            pb0 = *(const float4*)(Bg + (size_t)(k0 + 16) * N);
            pb1 = *(const float4*)(Bg + (size_t)(k0 + 17) * N);
        }

        {
            unsigned af[2][4], bf[8][2];
#pragma unroll
            for (int mt = 0; mt < 2; mt++) {
                int row = wm + (mt << 4) + g;
                af[mt][0] = As[row * ASTR2 + tg];
                af[mt][1] = As[(row + 8) * ASTR2 + tg];
                af[mt][2] = As[row * ASTR2 + tg + 4];
                af[mt][3] = As[(row + 8) * ASTR2 + tg + 4];
            }
#pragma unroll
            for (int nt = 0; nt < 8; nt++) {
                int c = wn + (nt << 3) + g;
                bf[nt][0] = Bs[tg * BSTR2 + c];
                bf[nt][1] = Bs[(tg + 4) * BSTR2 + c];
            }
#pragma unroll
            for (int mt = 0; mt < 2; mt++)
#pragma unroll
                for (int nt = 0; nt < 8; nt++)
                    mma_f16(acc[mt][nt], af[mt], bf[nt][0], bf[nt][1]);
        }
        __syncthreads();

        k0 += 16;
        if (!more) break;
    }

#pragma unroll
    for (int mt = 0; mt < 2; mt++) {
        int r0 = by + wm + (mt << 4) + g;
#pragma unroll
        for (int nt = 0; nt < 8; nt++) {
            int col = bx + wn + (nt << 3) + (tg << 1);
            float b0v = bias[col], b1v = bias[col + 1];
            *(unsigned*)&C[(size_t)r0 * N + col] =
                h2pack(acc[mt][nt][0] + b0v, acc[mt][nt][1] + b1v);
            *(unsigned*)&C[(size_t)(r0 + 8) * N + col] =
                h2pack(acc[mt][nt][2] + b0v, acc[mt][nt][3] + b1v);
        }
    }
}

// ---------------------------------------------------------------------------
// FP16 tensor-core GEMM, fp16 A input, fp32 output (unchanged from R11)
// ---------------------------------------------------------------------------
__global__ void __launch_bounds__(256) gemm_f16A_bias(
    int M, int N, int K,
    const __half* __restrict__ A, const float* __restrict__ B,
    const float* __restrict__ bias, float* __restrict__ C)
{
    __shared__ unsigned As[128 * ASTR2];
    __shared__ unsigned Bs[8 * BSTR2];

    const int tid  = threadIdx.x;
    const int lane = tid & 31, wid = tid >> 5;
    const int g  = lane >> 2, tg = lane & 3;
    const int wm = (wid & 3) << 5;
    const int wn = (wid >> 2) << 6;
    const int bx = blockIdx.x << 7, by = blockIdx.y << 7;

    const int ar = tid >> 1, ah = (tid & 1) << 3;
    const __half* Ag = A + (size_t)(by + ar) * K + ah;
    const int bk2 = tid >> 5, bn = (tid & 31) << 2;
    const float* Bg = B + (size_t)(2 * bk2) * N + bx + bn;

    uint4  pa  = *(const uint4*)(Ag);
    float4 pb0 = *(const float4*)(Bg);
    float4 pb1 = *(const float4*)(Bg + (size_t)N);

    float acc[2][8][4];
#pragma unroll
    for (int i = 0; i < 2; i++)
#pragma unroll
        for (int j = 0; j < 8; j++)
#pragma unroll
            for (int l = 0; l < 4; l++) acc[i][j][l] = 0.f;

    for (int k0 = 0; ; ) {
        {
            *(uint4*)&As[ar * ASTR2 + (ah >> 1)] = pa;
            uint4 vb = make_uint4(h2pack(pb0.x, pb1.x), h2pack(pb0.y, pb1.y),
                                  h2pack(pb0.z, pb1.z), h2pack(pb0.w, pb1.w));
            *(uint4*)&Bs[bk2 * BSTR2 + bn] = vb;
        }
        __syncthreads();

        bool more = (k0 + 16) < K;
        if (more) {
            pa  = *(const uint4*)(Ag + k0 + 16);
            pb0 = *(const float4*)(Bg + (size_t)(k0 + 16) * N);
            pb1 = *(const float4*)(Bg + (size_t)(k0 + 17) * N);
        }

        {
            unsigned af[2][4], bf[8][2];
#pragma unroll
            for (int mt = 0; mt < 2; mt++) {
                int row = wm + (mt << 4) + g;
                af[mt][0] = As[row * ASTR2 + tg];
                af[mt][1] = As[(row + 8) * ASTR2 + tg];
                af[mt][2] = As[row * ASTR2 + tg + 4];
                af[mt][3] = As[(row + 8) * ASTR2 + tg + 4];
            }
#pragma unroll
            for (int nt = 0; nt < 8; nt++) {
                int c = wn + (nt << 3) + g;
                bf[nt][0] = Bs[tg * BSTR2 + c];
                bf[nt][1] = Bs[(tg + 4) * BSTR2 + c];
            }
#pragma unroll
            for (int mt = 0; mt < 2; mt++)
#pragma unroll
                for (int nt = 0; nt < 8; nt++)
                    mma_f16(acc[mt][nt], af[mt], bf[nt][0], bf[nt][1]);
        }
        __syncthreads();

        k0 += 16;
        if (!more) break;
    }

#pragma unroll
    for (int mt = 0; mt < 2; mt++) {
        int r0 = by + wm + (mt << 4) + g;
#pragma unroll
        for (int nt = 0; nt < 8; nt++) {
            int col = bx + wn + (nt << 3) + (tg << 1);
            float b0v = bias[col], b1v = bias[col + 1];
            float2 v0 = make_float2(acc[mt][nt][0] + b0v, acc[mt][nt][1] + b1v);
            float2 v1 = make_float2(acc[mt][nt][2] + b0v, acc[mt][nt][3] + b1v);
            *(float2*)&C[(size_t)r0 * N + col]       = v0;
            *(float2*)&C[(size_t)(r0 + 8) * N + col] = v1;
        }
    }
}

// ---------------------------------------------------------------------------
// Persistent recurrent scan, v10: TWO independent pipelines per SM.
// 256 CTAs x 256 threads (8 warps), __launch_bounds__(256,2) + 50KB smem ->
// guaranteed 2 CTAs/SM co-resident. Unit = 16 batches x 16 j cols.
// Warp s: k-slice [128s,128s+128) (k2 in [64s,64s+64), 8 chunks), 2 n-tiles,
// 16 MMAs fp32-acc. Reduction depth 8. Counting wflag: 8 warp releases/step
// (target 8t). Back-pressure: 64 consumer rflags (warp 7, 2 acquires/lane).
// Same proven release/acquire protocol as R8-R11, scaled.
//
// SMEM (u32): W2 [512 k2][16 j] swizzled (32KB) | Red0/Red1 8*272 floats each
// ---------------------------------------------------------------------------
#define SCAN_THREADS 256
#define RSTR 272
#define SMEM_U32 (8192 + 2 * 8 * RSTR)

__global__ void __launch_bounds__(SCAN_THREADS, 2) rnn_scan_kernel(
    const float* __restrict__ W_hh, float* __restrict__ out)
{
    extern __shared__ unsigned smu[];
    unsigned* W2   = smu;                    // [512][16] fp16x2, swizzled (32KB)
    float*    Red0 = (float*)(smu + 8192);   // 8*272 floats
    float*    Red1 = Red0 + 8 * RSTR;

    const int cta = blockIdx.x;          // 0..255
    const int g   = cta >> 6;            // batch group 0..3
    const int cg  = cta & 63;            // col group 0..63 (16 j each)
    const int gb0 = g << 4;
    const int gj0 = cg << 4;
    const int tid = threadIdx.x;
    const int lane = tid & 31;
    const int s    = tid >> 5;           // warp id 0..7 = k-slice
    const int tg   = lane & 3;
    const int r    = lane >> 2;          // 0..7
    const int k2base = s << 6;           // 64s

    // one-time: W_hh[:, gj0:gj0+16] -> fp16 k-pairs, swizzled on (k2>>1)&1
    for (int i = 0; i < 32; ++i) {
        int idx = i * SCAN_THREADS + tid;    // 0..8191
        int k2 = idx >> 4, j = idx & 15;
        float w0 = W_hh[(size_t)(2 * k2) * RH + gj0 + j];
        float w1 = W_hh[(size_t)(2 * k2 + 1) * RH + gj0 + j];
        int dst = k2 * 16 + (j ^ (((k2 >> 1) & 1) << 3));
        W2[dst] = h2pack(w0, w1);
    }

    // finalize mapping: 256 threads = 16 b x 16 j
    const int fj = tid & 15;
    const int fb = tid >> 4;

    // producer flags: warp s consumes k2 [64s,64s+64) = j [128s,128s+128)
    // = producer CTAs (g, 8s + 0..7). Lanes 0-7 poll one each.
    const unsigned* prodflag =
        &g_wflag[((g << 6) + (s << 3) + (lane & 7)) * 32];
    // back-pressure: group g's 64 consumer rflags (warp 7: 2 per lane)
    const unsigned* grflag0 = &g_rflag[((g << 6) + lane) * 32];
    const unsigned* grflag1 = &g_rflag[((g << 6) + 32 + lane) * 32];
    unsigned* my_wflag = &g_wflag[cta * 32];
    unsigned* my_rflag = &g_rflag[cta * 32];

    // B-frag column (constant across chunks: (k2a>>1)&1 == tg>>1)
    const int c0base = r ^ ((tg >> 1) << 3);

    __syncthreads();   // W2 ready

    for (int t = 0; t < RT; ++t) {
        const unsigned bsrc = (unsigned)(t & 3) * (512 * 64);
        const unsigned bdst = (unsigned)((t + 1) & 3) * (512 * 64);
        float* RedT = (t & 1) ? Red1 : Red0;

        // x_proj prefetch (independent of flags)
        const size_t xpi = ((size_t)(gb0 + fb) * RT + t) * RH + gj0 + fj;
        const float xpv = __half2float(__ushort_as_half(ld_u16_cs(&g_xp[xpi])));

        // 1) wait for this warp's 8 producers (counting flags >= 8t)
        if (t > 0) {
            const unsigned tgt = 8u * (unsigned)t;
            if (lane < 8) {
                while (flag_acquire(prodflag) < tgt) { }
            }
            __syncwarp();
        }
        // warp 7: early-load group read-acks
        unsigned rv0 = 0, rv1 = 0;
        if (s == 7) { rv0 = flag_acquire(grflag0); rv1 = flag_acquire(grflag1); }

        // 2) direct LDG of A-fragments (32 x LDG.32, high MLP)
        unsigned ah[8][4];
#pragma unroll
        for (int cc = 0; cc < 8; ++cc) {
            const int k2a = k2base + (cc << 3) + tg;
            ah[cc][0] = ldcg_u32(&g_h2[bsrc + k2a * 64 + gb0 + r]);
            ah[cc][1] = ldcg_u32(&g_h2[bsrc + k2a * 64 + gb0 + r + 8]);
            ah[cc][2] = ldcg_u32(&g_h2[bsrc + (k2a + 4) * 64 + gb0 + r]);
            ah[cc][3] = ldcg_u32(&g_h2[bsrc + (k2a + 4) * 64 + gb0 + r + 8]);
        }

        // 3) 16 MMAs, fp32 accum (2 n-tiles x 8 chunks)
        float acc[2][4];
#pragma unroll
        for (int nt = 0; nt < 2; nt++)
#pragma unroll
            for (int l = 0; l < 4; l++) acc[nt][l] = 0.f;

#pragma unroll
        for (int cc = 0; cc < 8; ++cc) {
            const int k2a = k2base + (cc << 3) + tg;
#pragma unroll
            for (int nt = 0; nt < 2; ++nt) {
                const int c0 = (nt << 3) ^ c0base;   // ((nt<<3)+r) ^ ((tg>>1)<<3)
                mma_f16(acc[nt], ah[cc],
                        W2[k2a * 16 + ((nt << 3) | (c0base & 7)) ^ (c0base & 8)],
                        W2[(k2a + 4) * 16 + ((nt << 3) | (c0base & 7)) ^ (c0base & 8)]);
            }
        }

        // 4) write partials: RedT[s*272 + j*17 + b]
        {
            float* rp = RedT + s * RSTR;
#pragma unroll
            for (int nt = 0; nt < 2; ++nt) {
                int j0 = (nt << 3) + (tg << 1);
                rp[j0 * 17 + r]            = acc[nt][0];
                rp[(j0 + 1) * 17 + r]      = acc[nt][1];
                rp[j0 * 17 + r + 8]        = acc[nt][2];
                rp[(j0 + 1) * 17 + r + 8]  = acc[nt][3];
            }
        }
        // 5) warp 7: back-pressure — buf[(t+1)%4] free once all 64 rflags >= t-2
        if (s == 7) {
            int tgt = t - 2;
            if (tgt > 0) {
                while (!__all_sync(0xffffffffu,
                                   ((int)rv0 >= tgt) && ((int)rv1 >= tgt))) {
                    rv0 = flag_acquire(grflag0);
                    rv1 = flag_acquire(grflag1);
                }
            }
        }
        __syncthreads();   // Red complete, back-pressure verified, LDGs consumed

        // 6) publish read-ack
        if (tid == 0) flag_release(my_rflag, (unsigned)(t + 1));

        // 7) finalize: reduce 8 partials, tanh, store h, per-warp release
        {
            float v = 0.f;
            const float* rp = RedT + fj * 17 + fb;
#pragma unroll
            for (int ss = 0; ss < 8; ++ss) v += rp[ss * RSTR];
            float hv = tanhf(v + xpv);

            unsigned short hb = __half_as_ushort(__float2half_rn(hv));
            unsigned nb = __shfl_down_sync(0xffffffffu, (unsigned)hb, 1);
            if ((fj & 1) == 0) {
                int k2g = (cg << 3) + (fj >> 1);
                g_h2[bdst + k2g * 64 + gb0 + fb] =
                    (unsigned)hb | ((nb & 0xffffu) << 16);
            }
            __syncwarp();
            if (lane == 0) flag_red_add(my_wflag);   // warp's h visible -> count++

            st_u16_cs(&g_xp[xpi], hb);               // fp16 hidden history (GEMM3 in)
            if (t == RT - 1)
                out[(size_t)RB * RT * RO + (size_t)(gb0 + fb) * RH + gj0 + fj] = hv;
        }
    }
}

// ---------------------------------------------------------------------------
// Launch
// ---------------------------------------------------------------------------
extern "C" void kernel_launch(void* const* d_in, const int* in_sizes, int n_in,
                              void* d_out, int out_size)
{
    const float* inputs = (const float*)d_in[0];
    const float* h0     = (const float*)d_in[1];
    const float* W_xh   = (const float*)d_in[2];
    const float* W_hh   = (const float*)d_in[3];
    const float* W_hy   = (const float*)d_in[4];
    const float* b_h    = (const float*)d_in[5];
    const float* b_y    = (const float*)d_in[6];
    float* out = (float*)d_out;

    void* xp_ptr = nullptr;
    cudaGetSymbolAddress(&xp_ptr, g_xp);
    __half* xp = (__half*)xp_ptr;

    cudaFuncSetAttribute(rnn_scan_kernel,
                         cudaFuncAttributeMaxDynamicSharedMemorySize,
                         SMEM_U32 * (int)sizeof(unsigned));

    // 0) reset flags, seed h0 as fp16 pairs
    rnn_init<<<129, 256>>>(h0);

    // 1) x_proj = inputs @ W_xh + b_h   (fp16 TC, fp16 out)
    gemm_f16_bias_h16out<<<dim3(RH / 128, (RB * RT) / 128), 256>>>(
        RB * RT, RH, RI, inputs, W_xh, b_h, xp);

    // 2) persistent recurrent scan (256 CTAs, 2/SM)
    rnn_scan_kernel<<<256, SCAN_THREADS, SMEM_U32 * sizeof(unsigned)>>>(W_hh, out);

    // 3) outputs = hidden_states(fp16) @ W_hy + b_y   (fp16 TC)
    gemm_f16A_bias<<<dim3(RO / 128, (RB * RT) / 128), 256>>>(
        RB * RT, RO, RH, xp, W_hy, b_y, out);
}

// round 13
// speedup vs baseline: 1.0407x; 1.0407x over previous
#include <cuda_runtime.h>
#include <cuda_bf16.h>
#include <cuda_fp16.h>
#include <cstdint>
#include <cstddef>

// Problem constants
#define RB 64      // batch
#define RT 512     // time steps
#define RI 512     // input dim
#define RH 1024    // hidden dim
#define RO 512     // output dim
#define NBUF 4     // h ring-buffer depth

// ---------------------------------------------------------------------------
// Scratch (device globals; no allocation allowed)
// ---------------------------------------------------------------------------
__device__ __half g_xp[(size_t)RB * RT * RH];  // x_proj (fp16), then hidden states (in place)
__device__ unsigned g_h2[NBUF * 512 * 64];     // h fp16 k-pairs: [buf][k2][b]
__device__ unsigned g_wflag[128 * 32];         // per-CTA counting write flags (4 quadrants)
__device__ unsigned g_rflag[128 * 32];         // per-CTA read flags, 128B apart

// ---------------------------------------------------------------------------
// Helpers
// ---------------------------------------------------------------------------
// fp16 MMA, fp32 accumulate
__device__ __forceinline__ void mma_f16(float* d,
                                        const unsigned* a, unsigned b0, unsigned b1) {
    asm("mma.sync.aligned.m16n8k16.row.col.f32.f16.f16.f32 "
        "{%0,%1,%2,%3},{%4,%5,%6,%7},{%8,%9},{%0,%1,%2,%3};"
        : "+f"(d[0]), "+f"(d[1]), "+f"(d[2]), "+f"(d[3])
        : "r"(a[0]), "r"(a[1]), "r"(a[2]), "r"(a[3]),
          "r"(b0), "r"(b1));
}
__device__ __forceinline__ void flag_release(unsigned* p, unsigned v) {
    asm volatile("st.release.gpu.global.u32 [%0],%1;" :: "l"(p), "r"(v) : "memory");
}
__device__ __forceinline__ unsigned flag_acquire(const unsigned* p) {
    unsigned v;
    asm volatile("ld.acquire.gpu.global.u32 %0,[%1];" : "=r"(v) : "l"(p) : "memory");
    return v;
}
__device__ __forceinline__ void flag_red_add(unsigned* p) {
    asm volatile("red.release.gpu.global.add.u32 [%0],1;" :: "l"(p) : "memory");
}
__device__ __forceinline__ unsigned ldcg_u32(const unsigned* p) {
    unsigned v;
    asm volatile("ld.global.cg.u32 %0,[%1];" : "=r"(v) : "l"(p));
    return v;
}
__device__ __forceinline__ unsigned h2pack(float a, float b) {
    __half2 h = __floats2half2_rn(a, b);   // low = a, high = b
    return *reinterpret_cast<unsigned*>(&h);
}
__device__ __forceinline__ void st_u16_cs(__half* p, unsigned short v) {
    asm volatile("st.global.cs.u16 [%0],%1;" :: "l"(p), "h"(v) : "memory");
}
__device__ __forceinline__ unsigned short ld_u16_cs(const __half* p) {
    unsigned short v;
    asm volatile("ld.global.cs.u16 %0,[%1];" : "=h"(v) : "l"(p));
    return v;
}

// ---------------------------------------------------------------------------
// Init: zero flags, seed g_h2 buf0 from initial_hidden [b][j]
// ---------------------------------------------------------------------------
__global__ void rnn_init(const float* __restrict__ h0) {
    int bid = blockIdx.x;
    if (bid < 128) {
        int idx = bid * 256 + threadIdx.x;      // 0..32767 pairs
        int k2 = idx >> 6;                       // 0..511
        int b  = idx & 63;
        float v0 = h0[b * RH + 2 * k2];
        float v1 = h0[b * RH + 2 * k2 + 1];
        g_h2[k2 * 64 + b] = h2pack(v0, v1);
    } else {
        for (int i = threadIdx.x; i < 128 * 32; i += 256) {
            g_wflag[i] = 0;
            g_rflag[i] = 0;
        }
    }
}

// ---------------------------------------------------------------------------
// FP16 tensor-core GEMM, DOUBLE-BUFFERED smem (1 sync/iter):
//   C[M,N](fp16) = A[M,K](fp32) @ B[K,N](fp32) + bias[N]
// 128x128x16 tile, 256 thr = 8 warps (4x2), warp tile 32x64.
// ---------------------------------------------------------------------------
#define ASTR2 12
#define BSTR2 136
__global__ void __launch_bounds__(256) gemm_f16_bias_h16out(
    int M, int N, int K,
    const float* __restrict__ A, const float* __restrict__ B,
    const float* __restrict__ bias, __half* __restrict__ C)
{
    __shared__ unsigned As[2][128 * ASTR2];
    __shared__ unsigned Bs[2][8 * BSTR2];

    const int tid  = threadIdx.x;
    const int lane = tid & 31, wid = tid >> 5;
    const int g  = lane >> 2, tg = lane & 3;
    const int wm = (wid & 3) << 5;
    const int wn = (wid >> 2) << 6;
    const int bx = blockIdx.x << 7, by = blockIdx.y << 7;

    const int ar = tid >> 1, ah = (tid & 1) << 3;
    const float* Ag = A + (size_t)(by + ar) * K + ah;
    const int bk2 = tid >> 5, bn = (tid & 31) << 2;
    const float* Bg = B + (size_t)(2 * bk2) * N + bx + bn;

    const int nIters = K >> 4;

    float4 pa0, pa1, pb0, pb1;

    // tile 0 -> regs -> smem buf0
    pa0 = *(const float4*)(Ag);
    pa1 = *(const float4*)(Ag + 4);
    pb0 = *(const float4*)(Bg);
    pb1 = *(const float4*)(Bg + (size_t)N);
    {
        uint4 va = make_uint4(h2pack(pa0.x, pa0.y), h2pack(pa0.z, pa0.w),
                              h2pack(pa1.x, pa1.y), h2pack(pa1.z, pa1.w));
        *(uint4*)&As[0][ar * ASTR2 + (ah >> 1)] = va;
        uint4 vb = make_uint4(h2pack(pb0.x, pb1.x), h2pack(pb0.y, pb1.y),
                              h2pack(pb0.z, pb1.z), h2pack(pb0.w, pb1.w));
        *(uint4*)&Bs[0][bk2 * BSTR2 + bn] = vb;
    }
    __syncthreads();
    // prefetch tile 1
    if (nIters > 1) {
        pa0 = *(const float4*)(Ag + 16);
        pa1 = *(const float4*)(Ag + 20);
        pb0 = *(const float4*)(Bg + (size_t)16 * N);
        pb1 = *(const float4*)(Bg + (size_t)17 * N);
    }

    float acc[2][8][4];
#pragma unroll
    for (int i = 0; i < 2; i++)
#pragma unroll
        for (int j = 0; j < 8; j++)
#pragma unroll
            for (int l = 0; l < 4; l++) acc[i][j][l] = 0.f;

    for (int it = 0; it < nIters; ++it) {
        const int cur = it & 1;
        // store tile it+1 into the other buffer (read last in iter it-1; synced)
        if (it + 1 < nIters) {
            const int nxt = cur ^ 1;
            uint4 va = make_uint4(h2pack(pa0.x, pa0.y), h2pack(pa0.z, pa0.w),
                                  h2pack(pa1.x, pa1.y), h2pack(pa1.z, pa1.w));
            *(uint4*)&As[nxt][ar * ASTR2 + (ah >> 1)] = va;
            uint4 vb = make_uint4(h2pack(pb0.x, pb1.x), h2pack(pb0.y, pb1.y),
                                  h2pack(pb0.z, pb1.z), h2pack(pb0.w, pb1.w));
            *(uint4*)&Bs[nxt][bk2 * BSTR2 + bn] = vb;
        }

        // MMAs on current buffer
        {
            unsigned af[2][4], bf[8][2];
#pragma unroll
            for (int mt = 0; mt < 2; mt++) {
                int row = wm + (mt << 4) + g;
                af[mt][0] = As[cur][row * ASTR2 + tg];
                af[mt][1] = As[cur][(row + 8) * ASTR2 + tg];
                af[mt][2] = As[cur][row * ASTR2 + tg + 4];
                af[mt][3] = As[cur][(row + 8) * ASTR2 + tg + 4];
            }
#pragma unroll
            for (int nt = 0; nt < 8; nt++) {
                int c = wn + (nt << 3) + g;
                bf[nt][0] = Bs[cur][tg * BSTR2 + c];
                bf[nt][1] = Bs[cur][(tg + 4) * BSTR2 + c];
            }
#pragma unroll
            for (int mt = 0; mt < 2; mt++)
#pragma unroll
                for (int nt = 0; nt < 8; nt++)
                    mma_f16(acc[mt][nt], af[mt], bf[nt][0], bf[nt][1]);
        }
        __syncthreads();

        // prefetch tile it+2
        if (it + 2 < nIters) {
            int k0 = (it + 2) << 4;
            pa0 = *(const float4*)(Ag + k0);
            pa1 = *(const float4*)(Ag + k0 + 4);
            pb0 = *(const float4*)(Bg + (size_t)k0 * N);
            pb1 = *(const float4*)(Bg + (size_t)(k0 + 1) * N);
        }
    }

#pragma unroll
    for (int mt = 0; mt < 2; mt++) {
        int r0 = by + wm + (mt << 4) + g;
#pragma unroll
        for (int nt = 0; nt < 8; nt++) {
            int col = bx + wn + (nt << 3) + (tg << 1);
            float b0v = bias[col], b1v = bias[col + 1];
            *(unsigned*)&C[(size_t)r0 * N + col] =
                h2pack(acc[mt][nt][0] + b0v, acc[mt][nt][1] + b1v);
            *(unsigned*)&C[(size_t)(r0 + 8) * N + col] =
                h2pack(acc[mt][nt][2] + b0v, acc[mt][nt][3] + b1v);
        }
    }
}

// ---------------------------------------------------------------------------
// FP16 tensor-core GEMM, fp16 A input, fp32 output, DOUBLE-BUFFERED smem.
// ---------------------------------------------------------------------------
__global__ void __launch_bounds__(256) gemm_f16A_bias(
    int M, int N, int K,
    const __half* __restrict__ A, const float* __restrict__ B,
    const float* __restrict__ bias, float* __restrict__ C)
{
    __shared__ unsigned As[2][128 * ASTR2];
    __shared__ unsigned Bs[2][8 * BSTR2];

    const int tid  = threadIdx.x;
    const int lane = tid & 31, wid = tid >> 5;
    const int g  = lane >> 2, tg = lane & 3;
    const int wm = (wid & 3) << 5;
    const int wn = (wid >> 2) << 6;
    const int bx = blockIdx.x << 7, by = blockIdx.y << 7;

    const int ar = tid >> 1, ah = (tid & 1) << 3;
    const __half* Ag = A + (size_t)(by + ar) * K + ah;
    const int bk2 = tid >> 5, bn = (tid & 31) << 2;
    const float* Bg = B + (size_t)(2 * bk2) * N + bx + bn;

    const int nIters = K >> 4;

    uint4  pa;
    float4 pb0, pb1;

    pa  = *(const uint4*)(Ag);
    pb0 = *(const float4*)(Bg);
    pb1 = *(const float4*)(Bg + (size_t)N);
    {
        *(uint4*)&As[0][ar * ASTR2 + (ah >> 1)] = pa;
        uint4 vb = make_uint4(h2pack(pb0.x, pb1.x), h2pack(pb0.y, pb1.y),
                              h2pack(pb0.z, pb1.z), h2pack(pb0.w, pb1.w));
        *(uint4*)&Bs[0][bk2 * BSTR2 + bn] = vb;
    }
    __syncthreads();
    if (nIters > 1) {
        pa  = *(const uint4*)(Ag + 16);
        pb0 = *(const float4*)(Bg + (size_t)16 * N);
        pb1 = *(const float4*)(Bg + (size_t)17 * N);
    }

    float acc[2][8][4];
#pragma unroll
    for (int i = 0; i < 2; i++)
#pragma unroll
        for (int j = 0; j < 8; j++)
#pragma unroll
            for (int l = 0; l < 4; l++) acc[i][j][l] = 0.f;

    for (int it = 0; it < nIters; ++it) {
        const int cur = it & 1;
        if (it + 1 < nIters) {
            const int nxt = cur ^ 1;
            *(uint4*)&As[nxt][ar * ASTR2 + (ah >> 1)] = pa;
            uint4 vb = make_uint4(h2pack(pb0.x, pb1.x), h2pack(pb0.y, pb1.y),
                                  h2pack(pb0.z, pb1.z), h2pack(pb0.w, pb1.w));
            *(uint4*)&Bs[nxt][bk2 * BSTR2 + bn] = vb;
        }

        {
            unsigned af[2][4], bf[8][2];
#pragma unroll
            for (int mt = 0; mt < 2; mt++) {
                int row = wm + (mt << 4) + g;
                af[mt][0] = As[cur][row * ASTR2 + tg];
                af[mt][1] = As[cur][(row + 8) * ASTR2 + tg];
                af[mt][2] = As[cur][row * ASTR2 + tg + 4];
                af[mt][3] = As[cur][(row + 8) * ASTR2 + tg + 4];
            }
#pragma unroll
            for (int nt = 0; nt < 8; nt++) {
                int c = wn + (nt << 3) + g;
                bf[nt][0] = Bs[cur][tg * BSTR2 + c];
                bf[nt][1] = Bs[cur][(tg + 4) * BSTR2 + c];
            }
#pragma unroll
            for (int mt = 0; mt < 2; mt++)
#pragma unroll
                for (int nt = 0; nt < 8; nt++)
                    mma_f16(acc[mt][nt], af[mt], bf[nt][0], bf[nt][1]);
        }
        __syncthreads();

        if (it + 2 < nIters) {
            int k0 = (it + 2) << 4;
            pa  = *(const uint4*)(Ag + k0);
            pb0 = *(const float4*)(Bg + (size_t)k0 * N);
            pb1 = *(const float4*)(Bg + (size_t)(k0 + 1) * N);
        }
    }

#pragma unroll
    for (int mt = 0; mt < 2; mt++) {
        int r0 = by + wm + (mt << 4) + g;
#pragma unroll
        for (int nt = 0; nt < 8; nt++) {
            int col = bx + wn + (nt << 3) + (tg << 1);
            float b0v = bias[col], b1v = bias[col + 1];
            float2 v0 = make_float2(acc[mt][nt][0] + b0v, acc[mt][nt][1] + b1v);
            float2 v1 = make_float2(acc[mt][nt][2] + b0v, acc[mt][nt][3] + b1v);
            *(float2*)&C[(size_t)r0 * N + col]       = v0;
            *(float2*)&C[(size_t)(r0 + 8) * N + col] = v1;
        }
    }
}

// ---------------------------------------------------------------------------
// Persistent recurrent scan — R11 VERBATIM (proven best: 3.4us/step).
// 128 CTAs x 512 threads; single-fp16 h; 16 MMAs/warp fp32-acc; single
// barrier/step; counting quadrant releases; 4-deep ring; read-ack
// back-pressure; 8-lane flag polls.
// ---------------------------------------------------------------------------
#define SCAN_THREADS 512
#define SMEM_U32 (16384 + 2 * 16 * 544)

__global__ void __launch_bounds__(SCAN_THREADS) rnn_scan_kernel(
    const float* __restrict__ W_hh, float* __restrict__ out)
{
    extern __shared__ unsigned smu[];
    unsigned* W2   = smu;                     // [k2=512][32j] fp16x2, swizzled (64KB)
    float*    Red0 = (float*)(smu + 16384);
    float*    Red1 = Red0 + 16 * 544;

    const int cta = blockIdx.x;
    const int g   = cta >> 5;
    const int cg  = cta & 31;
    const int gb0 = g << 4;
    const int gj0 = cg << 5;
    const int tid = threadIdx.x;
    const int lane = tid & 31;
    const int s    = tid >> 5;
    const int tg   = lane & 3;
    const int r    = lane >> 2;
    const int k2base = s << 5;

    // one-time: W_hh[:, gj0:gj0+32] -> fp16 k-pairs, swizzled
    for (int i = 0; i < 32; ++i) {
        int idx = i * SCAN_THREADS + tid;
        int k2 = idx >> 5, j = idx & 31;
        float w0 = W_hh[(size_t)(2 * k2) * RH + gj0 + j];
        float w1 = W_hh[(size_t)(2 * k2 + 1) * RH + gj0 + j];
        int dst = k2 * 32 + (j ^ ((k2 & 3) << 3));
        W2[dst] = h2pack(w0, w1);
    }

    const int fb = tid >> 5;
    const int fj = tid & 31;

    const unsigned* prodflag =
        &g_wflag[((g << 5) + (s << 1) + (lane & 1)) * 32 + (((lane >> 1) & 3) << 3)];
    const unsigned* grflag = &g_rflag[((g << 5) + lane) * 32];
    unsigned* my_wflag_q = &g_wflag[cta * 32 + ((s & 3) << 3)];
    unsigned* my_rflag   = &g_rflag[cta * 32];

    __syncthreads();

    for (int t = 0; t < RT; ++t) {
        const unsigned bsrc = (unsigned)(t & 3) * (512 * 64);
        const unsigned bdst = (unsigned)((t + 1) & 3) * (512 * 64);
        float* RedT = (t & 1) ? Red1 : Red0;

        const size_t xpi = ((size_t)(gb0 + fb) * RT + t) * RH + gj0 + fj;
        const float xpv = __half2float(__ushort_as_half(ld_u16_cs(&g_xp[xpi])));

        // 1) wait for this warp's 2 producers (8 distinct flags, lanes 0-7)
        if (t > 0) {
            const unsigned tgt = 4u * (unsigned)t;
            if (lane < 8) {
                while (flag_acquire(prodflag) < tgt) { }
            }
            __syncwarp();
        }
        unsigned rv = 0;
        if (s == 15) rv = flag_acquire(grflag);

        // 2) direct LDG of A-fragments (16 x LDG.32)
        unsigned ah[4][4];
#pragma unroll
        for (int cc = 0; cc < 4; ++cc) {
            const int k2a = k2base + (cc << 3) + tg;
            ah[cc][0] = ldcg_u32(&g_h2[bsrc + k2a * 64 + gb0 + r]);
            ah[cc][1] = ldcg_u32(&g_h2[bsrc + k2a * 64 + gb0 + r + 8]);
            ah[cc][2] = ldcg_u32(&g_h2[bsrc + (k2a + 4) * 64 + gb0 + r]);
            ah[cc][3] = ldcg_u32(&g_h2[bsrc + (k2a + 4) * 64 + gb0 + r + 8]);
        }

        // 3) 16 MMAs, fp32 accum
        float acc[4][4];
#pragma unroll
        for (int nt = 0; nt < 4; nt++)
#pragma unroll
            for (int l = 0; l < 4; l++) acc[nt][l] = 0.f;

#pragma unroll
        for (int cc = 0; cc < 4; ++cc) {
            const int k2a = k2base + (cc << 3) + tg;
#pragma unroll
            for (int nt = 0; nt < 4; ++nt) {
                const int c0 = ((nt << 3) + r) ^ (tg << 3);
                mma_f16(acc[nt], ah[cc], W2[k2a * 32 + c0], W2[(k2a + 4) * 32 + c0]);
            }
        }

        // 4) write partials: RedT[s*544 + j*17 + b]
        {
            float* rp = RedT + s * 544;
#pragma unroll
            for (int nt = 0; nt < 4; ++nt) {
                int j0 = (nt << 3) + (tg << 1);
                rp[j0 * 17 + r]            = acc[nt][0];
                rp[(j0 + 1) * 17 + r]      = acc[nt][1];
                rp[j0 * 17 + r + 8]        = acc[nt][2];
                rp[(j0 + 1) * 17 + r + 8]  = acc[nt][3];
            }
        }
        // 5) warp 15: back-pressure
        if (s == 15) {
            int tgt = t - 2;
            if (tgt > 0) {
                while (!__all_sync(0xffffffffu, (int)rv >= tgt)) {
                    rv = flag_acquire(grflag);
                }
            }
        }
        __syncthreads();

        if (tid == 0) flag_release(my_rflag, (unsigned)(t + 1));

        // 7) finalize: reduce 16 partials, tanh, store h, release
        {
            float v = 0.f;
            const float* rp = RedT + fj * 17 + fb;
#pragma unroll
            for (int ss = 0; ss < 16; ++ss) v += rp[ss * 544];
            float hv = tanhf(v + xpv);

            unsigned short hb = __half_as_ushort(__float2half_rn(hv));
            unsigned nb = __shfl_down_sync(0xffffffffu, (unsigned)hb, 1);
            if ((fj & 1) == 0) {
                int k2g = (cg << 4) + (fj >> 1);
                g_h2[bdst + k2g * 64 + gb0 + fb] =
                    (unsigned)hb | ((nb & 0xffffu) << 16);
            }
            __syncwarp();
            if (lane == 0) flag_red_add(my_wflag_q);

            st_u16_cs(&g_xp[xpi], hb);   // fp16 hidden-state history (GEMM3 input)
            if (t == RT - 1)
                out[(size_t)RB * RT * RO + (size_t)(gb0 + fb) * RH + gj0 + fj] = hv;
        }
    }
}

// ---------------------------------------------------------------------------
// Launch
// ---------------------------------------------------------------------------
extern "C" void kernel_launch(void* const* d_in, const int* in_sizes, int n_in,
                              void* d_out, int out_size)
{
    const float* inputs = (const float*)d_in[0];
    const float* h0     = (const float*)d_in[1];
    const float* W_xh   = (const float*)d_in[2];
    const float* W_hh   = (const float*)d_in[3];
    const float* W_hy   = (const float*)d_in[4];
    const float* b_h    = (const float*)d_in[5];
    const float* b_y    = (const float*)d_in[6];
    float* out = (float*)d_out;

    void* xp_ptr = nullptr;
    cudaGetSymbolAddress(&xp_ptr, g_xp);
    __half* xp = (__half*)xp_ptr;

    cudaFuncSetAttribute(rnn_scan_kernel,
                         cudaFuncAttributeMaxDynamicSharedMemorySize,
                         SMEM_U32 * (int)sizeof(unsigned));

    // 0) reset flags, seed h0 as fp16 pairs
    rnn_init<<<129, 256>>>(h0);

    // 1) x_proj = inputs @ W_xh + b_h   (fp16 TC, double-buffered, fp16 out)
    gemm_f16_bias_h16out<<<dim3(RH / 128, (RB * RT) / 128), 256>>>(
        RB * RT, RH, RI, inputs, W_xh, b_h, xp);

    // 2) persistent recurrent scan (R11 proven config: 128 CTAs, 512 thr)
    rnn_scan_kernel<<<128, SCAN_THREADS, SMEM_U32 * sizeof(unsigned)>>>(W_hh, out);

    // 3) outputs = hidden_states(fp16) @ W_hy + b_y   (fp16 TC, double-buffered)
    gemm_f16A_bias<<<dim3(RO / 128, (RB * RT) / 128), 256>>>(
        RB * RT, RO, RH, xp, W_hy, b_y, out);
}